// round 12
// baseline (speedup 1.0000x reference)
#include <cuda_runtime.h>
#include <cuda_fp16.h>
#include <cstdint>

#define IN_F    4096
#define OUT_F   14336
#define GROUPSZ 128
#define KROT    8
#define BATCH   16
#define NPAIR   (IN_F/2)         // 2048 pairs per layer
#define NPACKED (OUT_F/8)        // 1792 packed int32 cols
#define KSPLIT  8
#define KRANGE  (IN_F/KSPLIT)    // 512
#define TILE_K  64
#define NTILES  (KRANGE/TILE_K)  // 8
#define GRP_BLK (KRANGE/GROUPSZ) // 4 groups per block
#define NBLK    128              // output cols per block
#define NPACK_BLK 16
#define NBLOCKS (OUT_F/NBLK)     // 112
#define A_STRIDE (KRANGE+8)      // 520 halves
#define B_STRIDE (NBLK+8)        // 136 halves (272B = 17*16B)

// device scratch (no allocations allowed)
__device__ __align__(16) __half g_A[BATCH*IN_F];        // rotated+scaled, row-major
__device__ __align__(16) float  g_part[KSPLIT*BATCH*OUT_F];

union U32H2 { uint32_t u; __half2 h; };
__device__ __forceinline__ __half2 u2h(uint32_t v){ U32H2 x; x.u=v; return x.h; }
__device__ __forceinline__ uint32_t h2u(__half2 h){ U32H2 x; x.h=h; return x.u; }
__device__ __forceinline__ uint32_t extrA(uint32_t q){ return (q & 0x000F000Fu) | 0x64006400u; }
__device__ __forceinline__ uint32_t extrB(uint32_t q){ return (q & 0x00F000F0u) | 0x64006400u; }

// ---------------------------------------------------------------- rotate ----
// block b owns batch rows {2b, 2b+1}; full activation in smem as half2[4096].
// all 8 layers in-block. __sincosf (MUFU fast path; |theta|<0.7 << pi, abs err
// ~5e-7, far below fp16 ulp) + next-layer prefetch of pairs/theta.
__global__ __launch_bounds__(512) void rotate_kernel(
    const float* __restrict__ x,
    const float* __restrict__ theta,
    const int*   __restrict__ pairs,
    const float* __restrict__ csc)
{
    __shared__ __half2 sx[IN_F];                     // 16 KB
    const int tid = threadIdx.x;
    const int b2  = blockIdx.x;                      // 0..7
    const float* r0 = x + (size_t)(2*b2  )*IN_F;
    const float* r1 = x + (size_t)(2*b2+1)*IN_F;

    // prefetch layer 0 metadata while loading activations
    int2  pr[4];
    float th[4];
    #pragma unroll
    for (int p = 0; p < 4; p++) {
        int j = p*512 + tid;
        pr[p] = reinterpret_cast<const int2*>(pairs)[j];
        th[p] = theta[j];
    }
    for (int c = tid; c < IN_F; c += 512)            // coalesced per row
        sx[c] = __halves2half2(__float2half(r0[c]), __float2half(r1[c]));
    __syncthreads();

    for (int k = 0; k < KROT; k++) {
        // fast sincos for current layer (independent MUFU chains)
        __half2 C[4], S[4];
        #pragma unroll
        for (int p = 0; p < 4; p++) {
            float sf, cf; __sincosf(th[p], &sf, &cf);
            C[p] = __half2half2(__float2half(cf));
            S[p] = __half2half2(__float2half(sf));
        }
        int2 cur[4];
        #pragma unroll
        for (int p = 0; p < 4; p++) cur[p] = pr[p];
        // prefetch next layer's metadata (overlaps smem work below)
        if (k+1 < KROT) {
            #pragma unroll
            for (int p = 0; p < 4; p++) {
                int j = (k+1)*NPAIR + p*512 + tid;
                pr[p] = reinterpret_cast<const int2*>(pairs)[j];
                th[p] = theta[j];
            }
        }
        #pragma unroll
        for (int p = 0; p < 4; p++) {
            __half2 a = sx[cur[p].x], bb = sx[cur[p].y];
            // exact per-op fp16 rounding; pairs within a layer are disjoint
            sx[cur[p].x] = __hsub2(__hmul2(C[p], a), __hmul2(S[p], bb));
            sx[cur[p].y] = __hadd2(__hmul2(S[p], a), __hmul2(C[p], bb));
        }
        __syncthreads();
    }

    // epilogue: channel scales, write both rows coalesced (half2 stores)
    __half2* oa = reinterpret_cast<__half2*>(g_A + (size_t)(2*b2  )*IN_F);
    __half2* ob = reinterpret_cast<__half2*>(g_A + (size_t)(2*b2+1)*IN_F);
    for (int i = tid; i < IN_F/2; i += 512) {
        int c = 2*i;
        __half2 v0 = sx[c], v1 = sx[c+1];            // {rowA, rowB} per channel
        __half2 sc = __halves2half2(__float2half(csc[c]), __float2half(csc[c+1]));
        oa[i] = __hmul2(__lows2half2 (v0, v1), sc);
        ob[i] = __hmul2(__highs2half2(v0, v1), sc);
    }
}

// ------------------------------------------------------------------ gemm ----
// KSPLIT=8: 896 blocks x 256 threads (~6 CTA/SM -> barriers hidden by overlap)
__global__ __launch_bounds__(256) void gemm_kernel(
    const int*   __restrict__ qweight,
    const int*   __restrict__ qzeros,
    const float* __restrict__ scales)
{
    __shared__ __half sA[BATCH*A_STRIDE];
    __shared__ __half sB[TILE_K*B_STRIDE];
    __shared__ uint4  lutZ[GRP_BLK*NPACK_BLK];
    __shared__ uint4  lutS[GRP_BLK*NPACK_BLK];

    const int tid = threadIdx.x;
    const int nb  = blockIdx.x;
    const int ksp = blockIdx.y;
    const int kb0 = ksp * KRANGE;
    const int npb = nb * NPACK_BLK;

    for (int i = tid; i < BATCH*KRANGE/8; i += 256) {
        int r = i >> 6, c = i & 63;
        uint4 v = reinterpret_cast<const uint4*>(g_A + r*IN_F + kb0)[c];
        reinterpret_cast<uint4*>(sA + r*A_STRIDE)[c] = v;
    }
    if (tid < GRP_BLK*NPACK_BLK) {
        int g = tid >> 4, p = tid & 15;
        int gg = ksp*GRP_BLK + g;
        uint32_t zq  = (uint32_t)qzeros[gg*NPACKED + npb + p];
        uint32_t zq2 = zq >> 8;
        lutZ[tid] = make_uint4(extrA(zq), extrB(zq), extrA(zq2), extrB(zq2));
        const float* sp = scales + (size_t)gg*OUT_F + (npb+p)*8;
        float4 sv0 = reinterpret_cast<const float4*>(sp)[0];
        float4 sv1 = reinterpret_cast<const float4*>(sp)[1];
        __half2 six = __half2half2(__float2half(0.0625f));   // exact 1/16
        __half2 S0 = __halves2half2(__float2half(sv0.x), __float2half(sv1.x));
        __half2 S1 = __hmul2(__halves2half2(__float2half(sv0.y), __float2half(sv1.y)), six);
        __half2 S2 = __halves2half2(__float2half(sv0.z), __float2half(sv1.z));
        __half2 S3 = __hmul2(__halves2half2(__float2half(sv0.w), __float2half(sv1.w)), six);
        lutS[tid] = make_uint4(h2u(S0), h2u(S1), h2u(S2), h2u(S3));
    }
    __syncthreads();

    const int kl   = tid >> 2;
    const int pq   = (tid & 3) * 4;
    const int warp = tid >> 5;
    const int lane = tid & 31;
    const int g8   = lane >> 2;
    const int t4   = lane & 3;

    float acc[2][4];
    #pragma unroll
    for (int j=0;j<2;j++){ acc[j][0]=acc[j][1]=acc[j][2]=acc[j][3]=0.f; }

    uint4 q = reinterpret_cast<const uint4*>(qweight + (size_t)(kb0 + kl)*NPACKED + npb + pq)[0];

    for (int t = 0; t < NTILES; t++) {
        {
            int g = t >> 1;
            uint32_t qq[4] = {q.x, q.y, q.z, q.w};
            #pragma unroll
            for (int u = 0; u < 4; u++) {
                int p = pq + u;
                uint4 zz = lutZ[g*16 + p];
                uint4 ss = lutS[g*16 + p];
                uint32_t qu  = qq[u];
                uint32_t qu2 = qu >> 8;
                __half2 w0 = __hmul2(__hsub2(u2h(extrA(qu )), u2h(zz.x)), u2h(ss.x));
                __half2 w1 = __hmul2(__hsub2(u2h(extrB(qu )), u2h(zz.y)), u2h(ss.y));
                __half2 w2 = __hmul2(__hsub2(u2h(extrA(qu2)), u2h(zz.z)), u2h(ss.z));
                __half2 w3 = __hmul2(__hsub2(u2h(extrB(qu2)), u2h(zz.w)), u2h(ss.w));
                __half2 n01 = __lows2half2 (w0, w1);
                __half2 n23 = __lows2half2 (w2, w3);
                __half2 n45 = __highs2half2(w0, w1);
                __half2 n67 = __highs2half2(w2, w3);
                reinterpret_cast<uint4*>(sB + kl*B_STRIDE + p*8)[0] =
                    make_uint4(h2u(n01), h2u(n23), h2u(n45), h2u(n67));
            }
        }
        __syncthreads();
        uint4 qn = q;
        if (t + 1 < NTILES)
            qn = reinterpret_cast<const uint4*>(
                qweight + (size_t)(kb0 + (t+1)*TILE_K + kl)*NPACKED + npb + pq)[0];
        #pragma unroll
        for (int kk = 0; kk < TILE_K/16; kk++) {
            int k0 = t*TILE_K + kk*16;
            int kb = kk*16;
            uint32_t a0 = *reinterpret_cast<const uint32_t*>(sA + (g8  )*A_STRIDE + k0 + 2*t4);
            uint32_t a1 = *reinterpret_cast<const uint32_t*>(sA + (g8+8)*A_STRIDE + k0 + 2*t4);
            uint32_t a2 = *reinterpret_cast<const uint32_t*>(sA + (g8  )*A_STRIDE + k0 + 2*t4 + 8);
            uint32_t a3 = *reinterpret_cast<const uint32_t*>(sA + (g8+8)*A_STRIDE + k0 + 2*t4 + 8);
            #pragma unroll
            for (int j = 0; j < 2; j++) {
                int n = warp*16 + j*8 + g8;
                __half2 b0h = __halves2half2(sB[(kb + 2*t4    )*B_STRIDE + n],
                                             sB[(kb + 2*t4 + 1)*B_STRIDE + n]);
                __half2 b1h = __halves2half2(sB[(kb + 2*t4 + 8)*B_STRIDE + n],
                                             sB[(kb + 2*t4 + 9)*B_STRIDE + n]);
                uint32_t b0 = h2u(b0h), b1 = h2u(b1h);
                asm volatile("mma.sync.aligned.m16n8k16.row.col.f32.f16.f16.f32 "
                    "{%0,%1,%2,%3}, {%4,%5,%6,%7}, {%8,%9}, {%0,%1,%2,%3};"
                    : "+f"(acc[j][0]),"+f"(acc[j][1]),"+f"(acc[j][2]),"+f"(acc[j][3])
                    : "r"(a0),"r"(a1),"r"(a2),"r"(a3),"r"(b0),"r"(b1));
            }
        }
        __syncthreads();
        q = qn;
    }

    float* outp = g_part + (size_t)ksp*BATCH*OUT_F;
    #pragma unroll
    for (int j = 0; j < 2; j++) {
        int col = nb*NBLK + warp*16 + j*8 + 2*t4;
        outp[(size_t)g8*OUT_F     + col    ] = acc[j][0];
        outp[(size_t)g8*OUT_F     + col + 1] = acc[j][1];
        outp[(size_t)(g8+8)*OUT_F + col    ] = acc[j][2];
        outp[(size_t)(g8+8)*OUT_F + col + 1] = acc[j][3];
    }
}

// ---------------------------------------------------------------- reduce ----
// output buffer is float32; round through fp16 to mirror reference output dtype
__global__ void reduce_kernel(float* __restrict__ out)
{
    int i = blockIdx.x*blockDim.x + threadIdx.x;
    if (i < BATCH*OUT_F/2) {
        float2 s = make_float2(0.f, 0.f);
        #pragma unroll
        for (int k = 0; k < KSPLIT; k++) {
            float2 v = reinterpret_cast<const float2*>(g_part + (size_t)k*BATCH*OUT_F)[i];
            s.x += v.x; s.y += v.y;
        }
        float2 r;
        r.x = __half2float(__float2half_rn(s.x));
        r.y = __half2float(__float2half_rn(s.y));
        reinterpret_cast<float2*>(out)[i] = r;
    }
}

// ---------------------------------------------------------------- launch ----
extern "C" void kernel_launch(void* const* d_in, const int* in_sizes, int n_in,
                              void* d_out, int out_size)
{
    const float* x     = (const float*)d_in[0];
    const float* theta = (const float*)d_in[1];
    const int*   pairs = (const int*)  d_in[2];
    const float* csc   = (const float*)d_in[3];
    const int*   qw    = (const int*)  d_in[4];
    const int*   qz    = (const int*)  d_in[5];
    const float* sc    = (const float*)d_in[6];
    (void)in_sizes; (void)n_in; (void)out_size;

    rotate_kernel<<<BATCH/2, 512>>>(x, theta, pairs, csc);
    gemm_kernel<<<dim3(NBLOCKS, KSPLIT), 256>>>(qw, qz, sc);
    reduce_kernel<<<(BATCH*OUT_F/2 + 255)/256, 256>>>((float*)d_out);
}

// round 14
// speedup vs baseline: 1.5090x; 1.5090x over previous
#include <cuda_runtime.h>
#include <cuda_fp16.h>
#include <cstdint>

#define IN_F    4096
#define OUT_F   14336
#define GROUPSZ 128
#define KROT    8
#define BATCH   16
#define NPAIR   (IN_F/2)         // 2048 pairs per layer
#define NPACKED (OUT_F/8)        // 1792 packed int32 cols
#define KSPLIT  8
#define KRANGE  (IN_F/KSPLIT)    // 512
#define TILE_K  64
#define NTILES  (KRANGE/TILE_K)  // 8
#define GRP_BLK (KRANGE/GROUPSZ) // 4 groups per block
#define NBLK    128              // output cols per block
#define NPACK_BLK 16
#define NBLOCKS (OUT_F/NBLK)     // 112
#define A_STRIDE (KRANGE+8)      // 520 halves
#define B_STRIDE (NBLK+8)        // 136 halves (272B = 17*16B)

#define ROT_T   1024             // rotate threads per block (32 warps)

// device scratch (no allocations allowed)
__device__ __align__(16) __half g_A[BATCH*IN_F];        // rotated+scaled, row-major
__device__ __align__(16) float  g_part[KSPLIT*BATCH*OUT_F];

union U32H2 { uint32_t u; __half2 h; };
__device__ __forceinline__ __half2 u2h(uint32_t v){ U32H2 x; x.u=v; return x.h; }
__device__ __forceinline__ uint32_t h2u(__half2 h){ U32H2 x; x.h=h; return x.u; }
__device__ __forceinline__ uint32_t extrA(uint32_t q){ return (q & 0x000F000Fu) | 0x64006400u; }
__device__ __forceinline__ uint32_t extrB(uint32_t q){ return (q & 0x00F000F0u) | 0x64006400u; }

// ---------------------------------------------------------------- rotate ----
// block b owns batch rows {2b, 2b+1}; full activation in smem as half2[4096].
// all 8 layers in-block. 1024 threads (32 warps) for latency hiding:
// 2 pairs/thread/layer, __sincosf (MUFU; |theta|<0.7, abs err ~5e-7 << fp16 ulp),
// next-layer metadata prefetch.
__global__ __launch_bounds__(ROT_T) void rotate_kernel(
    const float* __restrict__ x,
    const float* __restrict__ theta,
    const int*   __restrict__ pairs,
    const float* __restrict__ csc)
{
    __shared__ __half2 sx[IN_F];                     // 16 KB
    const int tid = threadIdx.x;
    const int b2  = blockIdx.x;                      // 0..7
    const float* r0 = x + (size_t)(2*b2  )*IN_F;
    const float* r1 = x + (size_t)(2*b2+1)*IN_F;

    // prefetch layer 0 metadata while loading activations
    int2  pr[2];
    float th[2];
    #pragma unroll
    for (int p = 0; p < 2; p++) {
        int j = p*ROT_T + tid;
        pr[p] = reinterpret_cast<const int2*>(pairs)[j];
        th[p] = theta[j];
    }
    #pragma unroll
    for (int p = 0; p < IN_F/ROT_T; p++) {
        int c = p*ROT_T + tid;
        sx[c] = __halves2half2(__float2half(r0[c]), __float2half(r1[c]));
    }
    __syncthreads();

    for (int k = 0; k < KROT; k++) {
        __half2 C[2], S[2];
        #pragma unroll
        for (int p = 0; p < 2; p++) {
            float sf, cf; __sincosf(th[p], &sf, &cf);
            C[p] = __half2half2(__float2half(cf));
            S[p] = __half2half2(__float2half(sf));
        }
        int2 cur[2];
        #pragma unroll
        for (int p = 0; p < 2; p++) cur[p] = pr[p];
        if (k+1 < KROT) {                            // prefetch next layer
            #pragma unroll
            for (int p = 0; p < 2; p++) {
                int j = (k+1)*NPAIR + p*ROT_T + tid;
                pr[p] = reinterpret_cast<const int2*>(pairs)[j];
                th[p] = theta[j];
            }
        }
        #pragma unroll
        for (int p = 0; p < 2; p++) {
            __half2 a = sx[cur[p].x], bb = sx[cur[p].y];
            // exact per-op fp16 rounding; pairs within a layer are disjoint
            sx[cur[p].x] = __hsub2(__hmul2(C[p], a), __hmul2(S[p], bb));
            sx[cur[p].y] = __hadd2(__hmul2(S[p], a), __hmul2(C[p], bb));
        }
        __syncthreads();
    }

    // epilogue: channel scales, write both rows coalesced (half2 stores)
    __half2* oa = reinterpret_cast<__half2*>(g_A + (size_t)(2*b2  )*IN_F);
    __half2* ob = reinterpret_cast<__half2*>(g_A + (size_t)(2*b2+1)*IN_F);
    #pragma unroll
    for (int p = 0; p < IN_F/2/ROT_T; p++) {
        int i = p*ROT_T + tid;
        int c = 2*i;
        __half2 v0 = sx[c], v1 = sx[c+1];            // {rowA, rowB} per channel
        __half2 sc = __halves2half2(__float2half(csc[c]), __float2half(csc[c+1]));
        oa[i] = __hmul2(__lows2half2 (v0, v1), sc);
        ob[i] = __hmul2(__highs2half2(v0, v1), sc);
    }
}

// ------------------------------------------------------------------ gemm ----
// KSPLIT=8: 896 blocks x 256 threads (~6 CTA/SM -> barriers hidden by overlap)
__global__ __launch_bounds__(256) void gemm_kernel(
    const int*   __restrict__ qweight,
    const int*   __restrict__ qzeros,
    const float* __restrict__ scales)
{
    __shared__ __half sA[BATCH*A_STRIDE];
    __shared__ __half sB[TILE_K*B_STRIDE];
    __shared__ uint4  lutZ[GRP_BLK*NPACK_BLK];
    __shared__ uint4  lutS[GRP_BLK*NPACK_BLK];

    const int tid = threadIdx.x;
    const int nb  = blockIdx.x;
    const int ksp = blockIdx.y;
    const int kb0 = ksp * KRANGE;
    const int npb = nb * NPACK_BLK;

    for (int i = tid; i < BATCH*KRANGE/8; i += 256) {
        int r = i >> 6, c = i & 63;
        uint4 v = reinterpret_cast<const uint4*>(g_A + r*IN_F + kb0)[c];
        reinterpret_cast<uint4*>(sA + r*A_STRIDE)[c] = v;
    }
    if (tid < GRP_BLK*NPACK_BLK) {
        int g = tid >> 4, p = tid & 15;
        int gg = ksp*GRP_BLK + g;
        uint32_t zq  = (uint32_t)qzeros[gg*NPACKED + npb + p];
        uint32_t zq2 = zq >> 8;
        lutZ[tid] = make_uint4(extrA(zq), extrB(zq), extrA(zq2), extrB(zq2));
        const float* sp = scales + (size_t)gg*OUT_F + (npb+p)*8;
        float4 sv0 = reinterpret_cast<const float4*>(sp)[0];
        float4 sv1 = reinterpret_cast<const float4*>(sp)[1];
        __half2 six = __half2half2(__float2half(0.0625f));   // exact 1/16
        __half2 S0 = __halves2half2(__float2half(sv0.x), __float2half(sv1.x));
        __half2 S1 = __hmul2(__halves2half2(__float2half(sv0.y), __float2half(sv1.y)), six);
        __half2 S2 = __halves2half2(__float2half(sv0.z), __float2half(sv1.z));
        __half2 S3 = __hmul2(__halves2half2(__float2half(sv0.w), __float2half(sv1.w)), six);
        lutS[tid] = make_uint4(h2u(S0), h2u(S1), h2u(S2), h2u(S3));
    }
    __syncthreads();

    const int kl   = tid >> 2;
    const int pq   = (tid & 3) * 4;
    const int warp = tid >> 5;
    const int lane = tid & 31;
    const int g8   = lane >> 2;
    const int t4   = lane & 3;

    float acc[2][4];
    #pragma unroll
    for (int j=0;j<2;j++){ acc[j][0]=acc[j][1]=acc[j][2]=acc[j][3]=0.f; }

    uint4 q = reinterpret_cast<const uint4*>(qweight + (size_t)(kb0 + kl)*NPACKED + npb + pq)[0];

    for (int t = 0; t < NTILES; t++) {
        {
            int g = t >> 1;
            uint32_t qq[4] = {q.x, q.y, q.z, q.w};
            #pragma unroll
            for (int u = 0; u < 4; u++) {
                int p = pq + u;
                uint4 zz = lutZ[g*16 + p];
                uint4 ss = lutS[g*16 + p];
                uint32_t qu  = qq[u];
                uint32_t qu2 = qu >> 8;
                __half2 w0 = __hmul2(__hsub2(u2h(extrA(qu )), u2h(zz.x)), u2h(ss.x));
                __half2 w1 = __hmul2(__hsub2(u2h(extrB(qu )), u2h(zz.y)), u2h(ss.y));
                __half2 w2 = __hmul2(__hsub2(u2h(extrA(qu2)), u2h(zz.z)), u2h(ss.z));
                __half2 w3 = __hmul2(__hsub2(u2h(extrB(qu2)), u2h(zz.w)), u2h(ss.w));
                __half2 n01 = __lows2half2 (w0, w1);
                __half2 n23 = __lows2half2 (w2, w3);
                __half2 n45 = __highs2half2(w0, w1);
                __half2 n67 = __highs2half2(w2, w3);
                reinterpret_cast<uint4*>(sB + kl*B_STRIDE + p*8)[0] =
                    make_uint4(h2u(n01), h2u(n23), h2u(n45), h2u(n67));
            }
        }
        __syncthreads();
        uint4 qn = q;
        if (t + 1 < NTILES)
            qn = reinterpret_cast<const uint4*>(
                qweight + (size_t)(kb0 + (t+1)*TILE_K + kl)*NPACKED + npb + pq)[0];
        #pragma unroll
        for (int kk = 0; kk < TILE_K/16; kk++) {
            int k0 = t*TILE_K + kk*16;
            int kb = kk*16;
            uint32_t a0 = *reinterpret_cast<const uint32_t*>(sA + (g8  )*A_STRIDE + k0 + 2*t4);
            uint32_t a1 = *reinterpret_cast<const uint32_t*>(sA + (g8+8)*A_STRIDE + k0 + 2*t4);
            uint32_t a2 = *reinterpret_cast<const uint32_t*>(sA + (g8  )*A_STRIDE + k0 + 2*t4 + 8);
            uint32_t a3 = *reinterpret_cast<const uint32_t*>(sA + (g8+8)*A_STRIDE + k0 + 2*t4 + 8);
            #pragma unroll
            for (int j = 0; j < 2; j++) {
                int n = warp*16 + j*8 + g8;
                __half2 b0h = __halves2half2(sB[(kb + 2*t4    )*B_STRIDE + n],
                                             sB[(kb + 2*t4 + 1)*B_STRIDE + n]);
                __half2 b1h = __halves2half2(sB[(kb + 2*t4 + 8)*B_STRIDE + n],
                                             sB[(kb + 2*t4 + 9)*B_STRIDE + n]);
                uint32_t b0 = h2u(b0h), b1 = h2u(b1h);
                asm volatile("mma.sync.aligned.m16n8k16.row.col.f32.f16.f16.f32 "
                    "{%0,%1,%2,%3}, {%4,%5,%6,%7}, {%8,%9}, {%0,%1,%2,%3};"
                    : "+f"(acc[j][0]),"+f"(acc[j][1]),"+f"(acc[j][2]),"+f"(acc[j][3])
                    : "r"(a0),"r"(a1),"r"(a2),"r"(a3),"r"(b0),"r"(b1));
            }
        }
        __syncthreads();
        q = qn;
    }

    float* outp = g_part + (size_t)ksp*BATCH*OUT_F;
    #pragma unroll
    for (int j = 0; j < 2; j++) {
        int col = nb*NBLK + warp*16 + j*8 + 2*t4;
        outp[(size_t)g8*OUT_F     + col    ] = acc[j][0];
        outp[(size_t)g8*OUT_F     + col + 1] = acc[j][1];
        outp[(size_t)(g8+8)*OUT_F + col    ] = acc[j][2];
        outp[(size_t)(g8+8)*OUT_F + col + 1] = acc[j][3];
    }
}

// ---------------------------------------------------------------- reduce ----
// output buffer is float32; round through fp16 to mirror reference output dtype
__global__ void reduce_kernel(float* __restrict__ out)
{
    int i = blockIdx.x*blockDim.x + threadIdx.x;
    if (i < BATCH*OUT_F/2) {
        float2 s = make_float2(0.f, 0.f);
        #pragma unroll
        for (int k = 0; k < KSPLIT; k++) {
            float2 v = reinterpret_cast<const float2*>(g_part + (size_t)k*BATCH*OUT_F)[i];
            s.x += v.x; s.y += v.y;
        }
        float2 r;
        r.x = __half2float(__float2half_rn(s.x));
        r.y = __half2float(__float2half_rn(s.y));
        reinterpret_cast<float2*>(out)[i] = r;
    }
}

// ---------------------------------------------------------------- launch ----
extern "C" void kernel_launch(void* const* d_in, const int* in_sizes, int n_in,
                              void* d_out, int out_size)
{
    const float* x     = (const float*)d_in[0];
    const float* theta = (const float*)d_in[1];
    const int*   pairs = (const int*)  d_in[2];
    const float* csc   = (const float*)d_in[3];
    const int*   qw    = (const int*)  d_in[4];
    const int*   qz    = (const int*)  d_in[5];
    const float* sc    = (const float*)d_in[6];
    (void)in_sizes; (void)n_in; (void)out_size;

    rotate_kernel<<<BATCH/2, ROT_T>>>(x, theta, pairs, csc);
    gemm_kernel<<<dim3(NBLOCKS, KSPLIT), 256>>>(qw, qz, sc);
    reduce_kernel<<<(BATCH*OUT_F/2 + 255)/256, 256>>>((float*)d_out);
}

// round 15
// speedup vs baseline: 1.6588x; 1.0993x over previous
#include <cuda_runtime.h>
#include <cuda_fp16.h>
#include <cstdint>

#define IN_F    4096
#define OUT_F   14336
#define GROUPSZ 128
#define KROT    8
#define BATCH   16
#define NPAIR   (IN_F/2)         // 2048 pairs per layer
#define NPACKED (OUT_F/8)        // 1792 packed int32 cols
#define KSPLIT  8
#define KRANGE  (IN_F/KSPLIT)    // 512
#define TILE_K  32               // smaller tile -> double buffer fits static smem
#define NTILES  (KRANGE/TILE_K)  // 16
#define GRP_BLK (KRANGE/GROUPSZ) // 4 groups per block
#define NBLK    128              // output cols per block
#define NPACK_BLK 16
#define NBLOCKS (OUT_F/NBLK)     // 112
#define A_STRIDE (KRANGE+8)      // 520 halves (1040B, 16B-aligned rows)
#define B_STRIDE (NBLK+8)        // 136 halves (272B = 17*16B)

#define ROT_T   1024             // rotate threads per block (32 warps)

// device scratch (no allocations allowed)
__device__ __align__(16) __half g_A[BATCH*IN_F];        // rotated+scaled, row-major
__device__ __align__(16) float  g_part[KSPLIT*BATCH*OUT_F];

union U32H2 { uint32_t u; __half2 h; };
__device__ __forceinline__ __half2 u2h(uint32_t v){ U32H2 x; x.u=v; return x.h; }
__device__ __forceinline__ uint32_t h2u(__half2 h){ U32H2 x; x.h=h; return x.u; }
__device__ __forceinline__ uint32_t extrA(uint32_t q){ return (q & 0x000F000Fu) | 0x64006400u; }
__device__ __forceinline__ uint32_t extrB(uint32_t q){ return (q & 0x00F000F0u) | 0x64006400u; }

// ---------------------------------------------------------------- rotate ----
// (unchanged from R14: 9.47us measured)
__global__ __launch_bounds__(ROT_T) void rotate_kernel(
    const float* __restrict__ x,
    const float* __restrict__ theta,
    const int*   __restrict__ pairs,
    const float* __restrict__ csc)
{
    __shared__ __half2 sx[IN_F];                     // 16 KB
    const int tid = threadIdx.x;
    const int b2  = blockIdx.x;                      // 0..7
    const float* r0 = x + (size_t)(2*b2  )*IN_F;
    const float* r1 = x + (size_t)(2*b2+1)*IN_F;

    int2  pr[2];
    float th[2];
    #pragma unroll
    for (int p = 0; p < 2; p++) {
        int j = p*ROT_T + tid;
        pr[p] = reinterpret_cast<const int2*>(pairs)[j];
        th[p] = theta[j];
    }
    #pragma unroll
    for (int p = 0; p < IN_F/ROT_T; p++) {
        int c = p*ROT_T + tid;
        sx[c] = __halves2half2(__float2half(r0[c]), __float2half(r1[c]));
    }
    __syncthreads();

    for (int k = 0; k < KROT; k++) {
        __half2 C[2], S[2];
        #pragma unroll
        for (int p = 0; p < 2; p++) {
            float sf, cf; __sincosf(th[p], &sf, &cf);
            C[p] = __half2half2(__float2half(cf));
            S[p] = __half2half2(__float2half(sf));
        }
        int2 cur[2];
        #pragma unroll
        for (int p = 0; p < 2; p++) cur[p] = pr[p];
        if (k+1 < KROT) {
            #pragma unroll
            for (int p = 0; p < 2; p++) {
                int j = (k+1)*NPAIR + p*ROT_T + tid;
                pr[p] = reinterpret_cast<const int2*>(pairs)[j];
                th[p] = theta[j];
            }
        }
        #pragma unroll
        for (int p = 0; p < 2; p++) {
            __half2 a = sx[cur[p].x], bb = sx[cur[p].y];
            sx[cur[p].x] = __hsub2(__hmul2(C[p], a), __hmul2(S[p], bb));
            sx[cur[p].y] = __hadd2(__hmul2(S[p], a), __hmul2(C[p], bb));
        }
        __syncthreads();
    }

    __half2* oa = reinterpret_cast<__half2*>(g_A + (size_t)(2*b2  )*IN_F);
    __half2* ob = reinterpret_cast<__half2*>(g_A + (size_t)(2*b2+1)*IN_F);
    #pragma unroll
    for (int p = 0; p < IN_F/2/ROT_T; p++) {
        int i = p*ROT_T + tid;
        int c = 2*i;
        __half2 v0 = sx[c], v1 = sx[c+1];
        __half2 sc = __halves2half2(__float2half(csc[c]), __float2half(csc[c+1]));
        oa[i] = __hmul2(__lows2half2 (v0, v1), sc);
        ob[i] = __hmul2(__highs2half2(v0, v1), sc);
    }
}

// ------------------------------------------------------------------ gemm ----
// KSPLIT=8: 896 blocks x 256 threads, 6 CTA/SM. Double-buffered sB (TILE_K=32):
// dequant(t+1) overlaps mma(t), ONE barrier per tile. ldmatrix fragment loads
// (verified identical mapping to the previous explicit per-thread LDS).
__global__ __launch_bounds__(256) void gemm_kernel(
    const int*   __restrict__ qweight,
    const int*   __restrict__ qzeros,
    const float* __restrict__ scales)
{
    __shared__ __half sA[BATCH*A_STRIDE];            // 16.25 KB
    __shared__ __half sB[2][TILE_K*B_STRIDE];        // 2 x 8.5 KB
    __shared__ uint4  lutZ[GRP_BLK*NPACK_BLK];       // 1 KB
    __shared__ uint4  lutS[GRP_BLK*NPACK_BLK];       // 1 KB

    const int tid = threadIdx.x;
    const int nb  = blockIdx.x;
    const int ksp = blockIdx.y;
    const int kb0 = ksp * KRANGE;
    const int npb = nb * NPACK_BLK;

    // ---- load A slice [16][512] into padded shared
    for (int i = tid; i < BATCH*KRANGE/8; i += 256) {
        int r = i >> 6, c = i & 63;
        reinterpret_cast<uint4*>(sA + r*A_STRIDE)[c] =
            reinterpret_cast<const uint4*>(g_A + r*IN_F + kb0)[c];
    }
    // ---- zero/scale LUT (4 groups x 16 packs), magic-extract pair order
    if (tid < GRP_BLK*NPACK_BLK) {
        int g = tid >> 4, p = tid & 15;
        int gg = ksp*GRP_BLK + g;
        uint32_t zq  = (uint32_t)qzeros[gg*NPACKED + npb + p];
        uint32_t zq2 = zq >> 8;
        lutZ[tid] = make_uint4(extrA(zq), extrB(zq), extrA(zq2), extrB(zq2));
        const float* sp = scales + (size_t)gg*OUT_F + (npb+p)*8;
        float4 sv0 = reinterpret_cast<const float4*>(sp)[0];
        float4 sv1 = reinterpret_cast<const float4*>(sp)[1];
        __half2 six = __half2half2(__float2half(0.0625f));   // exact 1/16
        __half2 S0 = __halves2half2(__float2half(sv0.x), __float2half(sv1.x));
        __half2 S1 = __hmul2(__halves2half2(__float2half(sv0.y), __float2half(sv1.y)), six);
        __half2 S2 = __halves2half2(__float2half(sv0.z), __float2half(sv1.z));
        __half2 S3 = __hmul2(__halves2half2(__float2half(sv0.w), __float2half(sv1.w)), six);
        lutS[tid] = make_uint4(h2u(S0), h2u(S1), h2u(S2), h2u(S3));
    }
    __syncthreads();

    const int kl   = tid >> 3;             // dequant row 0..31
    const int pq   = (tid & 7) * 2;        // pack pair base
    const int warp = tid >> 5;
    const int lane = tid & 31;

    float acc[2][4];
    #pragma unroll
    for (int j=0;j<2;j++){ acc[j][0]=acc[j][1]=acc[j][2]=acc[j][3]=0.f; }

    const uint32_t sA_base = (uint32_t)__cvta_generic_to_shared(sA);
    const uint32_t sB_base0 = (uint32_t)__cvta_generic_to_shared(sB[0]);
    const uint32_t sB_base1 = (uint32_t)__cvta_generic_to_shared(sB[1]);
    // ldmatrix lane address components (identical mapping to explicit loads)
    const uint32_t lrow = lane & 15;
    const uint32_t lcol8 = (lane >> 4) << 3;
    const uint32_t aoff = (uint32_t)(lrow*A_STRIDE + lcol8) * 2u;
    const uint32_t boff = (uint32_t)(lrow*B_STRIDE + warp*16 + lcol8) * 2u;

    // dequant one 32-K tile into a buffer: exact (n-z)*s single rounding
    auto dequant = [&](int t, uint2 qv, __half* dst) {
        int g = t >> 2;                    // group = (t*32)/128
        uint32_t qq[2] = {qv.x, qv.y};
        #pragma unroll
        for (int u = 0; u < 2; u++) {
            int p = pq + u;
            uint4 zz = lutZ[g*16 + p];
            uint4 ss = lutS[g*16 + p];
            uint32_t qu  = qq[u];
            uint32_t qu2 = qu >> 8;
            __half2 w0 = __hmul2(__hsub2(u2h(extrA(qu )), u2h(zz.x)), u2h(ss.x)); // {v0,v4}
            __half2 w1 = __hmul2(__hsub2(u2h(extrB(qu )), u2h(zz.y)), u2h(ss.y)); // {v1,v5}
            __half2 w2 = __hmul2(__hsub2(u2h(extrA(qu2)), u2h(zz.z)), u2h(ss.z)); // {v2,v6}
            __half2 w3 = __hmul2(__hsub2(u2h(extrB(qu2)), u2h(zz.w)), u2h(ss.w)); // {v3,v7}
            __half2 n01 = __lows2half2 (w0, w1);
            __half2 n23 = __lows2half2 (w2, w3);
            __half2 n45 = __highs2half2(w0, w1);
            __half2 n67 = __highs2half2(w2, w3);
            reinterpret_cast<uint4*>(dst + kl*B_STRIDE + p*8)[0] =
                make_uint4(h2u(n01), h2u(n23), h2u(n45), h2u(n67));
        }
    };
    auto ldq = [&](int t) {
        return reinterpret_cast<const uint2*>(
            qweight + (size_t)(kb0 + t*TILE_K + kl)*NPACKED + npb + pq)[0];
    };

    // ---- prologue: fill buffer 0, prefetch tile 1
    uint2 q0 = ldq(0);
    dequant(0, q0, sB[0]);
    uint2 qn = ldq(1);
    __syncthreads();

    #pragma unroll 2
    for (int t = 0; t < NTILES; t++) {
        // overlap: dequant tile t+1 into other buffer while mma consumes tile t
        if (t + 1 < NTILES) dequant(t+1, qn, sB[(t+1)&1]);
        if (t + 2 < NTILES) qn = ldq(t+2);

        const uint32_t bbase = (t & 1) ? sB_base1 : sB_base0;
        #pragma unroll
        for (int kk = 0; kk < TILE_K/16; kk++) {
            uint32_t a0,a1,a2,a3, b0,b1,b2,b3;
            uint32_t aaddr = sA_base + aoff + (uint32_t)(t*TILE_K + kk*16)*2u;
            asm volatile("ldmatrix.sync.aligned.m8n8.x4.shared.b16 {%0,%1,%2,%3}, [%4];"
                : "=r"(a0),"=r"(a1),"=r"(a2),"=r"(a3) : "r"(aaddr));
            uint32_t baddr = bbase + boff + (uint32_t)(kk*16*B_STRIDE)*2u;
            asm volatile("ldmatrix.sync.aligned.m8n8.x4.trans.shared.b16 {%0,%1,%2,%3}, [%4];"
                : "=r"(b0),"=r"(b1),"=r"(b2),"=r"(b3) : "r"(baddr));
            asm volatile("mma.sync.aligned.m16n8k16.row.col.f32.f16.f16.f32 "
                "{%0,%1,%2,%3}, {%4,%5,%6,%7}, {%8,%9}, {%0,%1,%2,%3};"
                : "+f"(acc[0][0]),"+f"(acc[0][1]),"+f"(acc[0][2]),"+f"(acc[0][3])
                : "r"(a0),"r"(a1),"r"(a2),"r"(a3),"r"(b0),"r"(b1));
            asm volatile("mma.sync.aligned.m16n8k16.row.col.f32.f16.f16.f32 "
                "{%0,%1,%2,%3}, {%4,%5,%6,%7}, {%8,%9}, {%0,%1,%2,%3};"
                : "+f"(acc[1][0]),"+f"(acc[1][1]),"+f"(acc[1][2]),"+f"(acc[1][3])
                : "r"(a0),"r"(a1),"r"(a2),"r"(a3),"r"(b2),"r"(b3));
        }
        if (t + 1 < NTILES) __syncthreads();
    }

    // ---- epilogue: fp32 partials (fragment row/col per PTX tables)
    const int g8 = lane >> 2;
    const int t4 = lane & 3;
    float* outp = g_part + (size_t)ksp*BATCH*OUT_F;
    #pragma unroll
    for (int j = 0; j < 2; j++) {
        int col = nb*NBLK + warp*16 + j*8 + 2*t4;
        outp[(size_t)g8*OUT_F     + col    ] = acc[j][0];
        outp[(size_t)g8*OUT_F     + col + 1] = acc[j][1];
        outp[(size_t)(g8+8)*OUT_F + col    ] = acc[j][2];
        outp[(size_t)(g8+8)*OUT_F + col + 1] = acc[j][3];
    }
}

// ---------------------------------------------------------------- reduce ----
__global__ void reduce_kernel(float* __restrict__ out)
{
    int i = blockIdx.x*blockDim.x + threadIdx.x;
    if (i < BATCH*OUT_F/2) {
        float2 s = make_float2(0.f, 0.f);
        #pragma unroll
        for (int k = 0; k < KSPLIT; k++) {
            float2 v = reinterpret_cast<const float2*>(g_part + (size_t)k*BATCH*OUT_F)[i];
            s.x += v.x; s.y += v.y;
        }
        float2 r;
        r.x = __half2float(__float2half_rn(s.x));
        r.y = __half2float(__float2half_rn(s.y));
        reinterpret_cast<float2*>(out)[i] = r;
    }
}

// ---------------------------------------------------------------- launch ----
extern "C" void kernel_launch(void* const* d_in, const int* in_sizes, int n_in,
                              void* d_out, int out_size)
{
    const float* x     = (const float*)d_in[0];
    const float* theta = (const float*)d_in[1];
    const int*   pairs = (const int*)  d_in[2];
    const float* csc   = (const float*)d_in[3];
    const int*   qw    = (const int*)  d_in[4];
    const int*   qz    = (const int*)  d_in[5];
    const float* sc    = (const float*)d_in[6];
    (void)in_sizes; (void)n_in; (void)out_size;

    rotate_kernel<<<BATCH/2, ROT_T>>>(x, theta, pairs, csc);
    gemm_kernel<<<dim3(NBLOCKS, KSPLIT), 256>>>(qw, qz, sc);
    reduce_kernel<<<(BATCH*OUT_F/2 + 255)/256, 256>>>((float*)d_out);
}